// round 3
// baseline (speedup 1.0000x reference)
#include <cuda_runtime.h>
#include <cuda_fp16.h>
#include <cstdint>
#include <cstddef>

// Problem dims (fixed for this dataset entry)
static constexpr int MM = 4096;
static constexpr int NN = 4096;
static constexpr int KK = 4096;
static constexpr int NG = 32;          // K / 128 groups

// fp16 staging buffers (static device globals: allowed scratch)
__device__ __half g_A[(size_t)MM * KK];   // x in fp16
__device__ __half g_B[(size_t)NN * KK];   // dequantized W in fp16

// ---------------------------------------------------------------------------
// Helpers (base-target PTX only: sm_80-level features, no tcgen05 / no 'a')
// ---------------------------------------------------------------------------
__device__ __forceinline__ uint32_t smem_u32(const void* p) {
    uint32_t a;
    asm("{ .reg .u64 t; cvta.to.shared.u64 t, %1; cvt.u32.u64 %0, t; }"
        : "=r"(a) : "l"(p));
    return a;
}

__device__ __forceinline__ void cp_async16(uint32_t dst, const void* src) {
    asm volatile("cp.async.cg.shared.global [%0], [%1], 16;"
                 :: "r"(dst), "l"(src));
}
__device__ __forceinline__ void cp_async_commit() {
    asm volatile("cp.async.commit_group;" ::: "memory");
}
__device__ __forceinline__ void cp_async_wait2() {
    asm volatile("cp.async.wait_group 2;" ::: "memory");
}

__device__ __forceinline__ void ldsm_x4(uint32_t* r, uint32_t addr) {
    asm volatile("ldmatrix.sync.aligned.m8n8.x4.shared.b16 {%0,%1,%2,%3}, [%4];"
                 : "=r"(r[0]), "=r"(r[1]), "=r"(r[2]), "=r"(r[3]) : "r"(addr));
}
__device__ __forceinline__ void ldsm_x2(uint32_t* r, uint32_t addr) {
    asm volatile("ldmatrix.sync.aligned.m8n8.x2.shared.b16 {%0,%1}, [%2];"
                 : "=r"(r[0]), "=r"(r[1]) : "r"(addr));
}

__device__ __forceinline__ void mma16816(float* c, const uint32_t* a, const uint32_t* b) {
    asm volatile("mma.sync.aligned.m16n8k16.row.col.f32.f16.f16.f32 "
                 "{%0,%1,%2,%3}, {%4,%5,%6,%7}, {%8,%9}, {%0,%1,%2,%3};"
                 : "+f"(c[0]), "+f"(c[1]), "+f"(c[2]), "+f"(c[3])
                 : "r"(a[0]), "r"(a[1]), "r"(a[2]), "r"(a[3]),
                   "r"(b[0]), "r"(b[1]));
}

// SW128 swizzle: XOR bits [6:4] with bits [9:7]
#define SWZ(o) ((o) ^ (((o) >> 3) & 0x70))

// ---------------------------------------------------------------------------
// Stage 1 kernels: fp32 -> fp16 convert, and LUT dequant of W
// ---------------------------------------------------------------------------
__global__ void __launch_bounds__(256) k_convert_x(const float* __restrict__ x) {
    size_t i = (size_t)blockIdx.x * 256 + threadIdx.x;   // float4 index
    float4 v = reinterpret_cast<const float4*>(x)[i];
    __half2* o = reinterpret_cast<__half2*>(g_A) + i * 2;
    o[0] = __floats2half2_rn(v.x, v.y);
    o[1] = __floats2half2_rn(v.z, v.w);
}

__global__ void __launch_bounds__(256) k_dequant_w(const int* __restrict__ q,
                                                   const float* __restrict__ scales,
                                                   const float* __restrict__ tables) {
    __shared__ float t[16];
    if (threadIdx.x < 16) t[threadIdx.x] = tables[threadIdx.x];
    __syncthreads();
    size_t i = (size_t)blockIdx.x * 256 + threadIdx.x;   // int4 index (4 q values)
    int4 qv = reinterpret_cast<const int4*>(q)[i];
    size_t e = i * 4;                                    // flat element index
    int n = (int)(e >> 12);                              // /4096
    int k = (int)(e & 4095);
    float s = scales[(size_t)n * NG + (k >> 7)];
    __half2* o = reinterpret_cast<__half2*>(g_B) + i * 2;
    o[0] = __floats2half2_rn(t[qv.x] * s, t[qv.y] * s);
    o[1] = __floats2half2_rn(t[qv.z] * s, t[qv.w] * s);
}

// ---------------------------------------------------------------------------
// Stage 2: mma.sync (HMMA.16816) GEMM  y[M,N] = A[M,K] * B[N,K]^T
// CTA tile 128x128, BK=64, 4-stage cp.async pipeline, 8 warps x (64x32)
// ---------------------------------------------------------------------------
static constexpr int STAGES = 4;
static constexpr int TILE_BYTES = 128 * 128;                 // 16KB per operand per stage
static constexpr int SMEM_BYTES = 1024 + STAGES * 2 * TILE_BYTES;  // align slack + tiles
static constexpr int KITERS = KK / 64;                       // 64

__device__ __forceinline__ void load_tile(uint32_t sA, uint32_t sB,
                                          const __half* gA, const __half* gB,
                                          int m0, int n0, int k0, int tid) {
#pragma unroll
    for (int i = 0; i < 4; i++) {
        int ci = tid + (i << 8);            // 0..1023 chunk id
        int r = ci >> 3, c = ci & 7;        // row, 16B chunk within row
        uint32_t off = SWZ(r * 128 + c * 16);
        cp_async16(sA + off, gA + (size_t)(m0 + r) * KK + k0 + (c << 3));
        cp_async16(sB + off, gB + (size_t)(n0 + r) * KK + k0 + (c << 3));
    }
    cp_async_commit();
}

__global__ void __launch_bounds__(256, 1)
qgemm(float* __restrict__ out) {
    extern __shared__ __align__(1024) char smem[];
    uint32_t sb = (smem_u32(smem) + 1023) & ~1023u;
    const int tid = threadIdx.x, wid = tid >> 5, lid = tid & 31;
    const int m0 = blockIdx.y << 7, n0 = blockIdx.x << 7;

    const uint32_t sA = sb;                          // STAGES x 16KB
    const uint32_t sB = sb + STAGES * TILE_BYTES;    // STAGES x 16KB

    // warp tile: 64 (M) x 32 (N)
    const int wm = (wid & 1) << 6;       // 0 or 64
    const int wn = (wid >> 1) << 5;      // 0,32,64,96

    // per-thread ldmatrix byte offsets (pre-swizzle, within a stage tile)
    uint32_t aoff[4], boff[4];
    {
        int arow = wm + (lid & 15);
        int acol = (lid >> 4) << 4;                  // 0 or 16 bytes
        int blane = lid & 15;
        int brow = wn + (blane & 7);
        int bcol = ((blane >> 3) & 1) << 4;          // 0 or 16 bytes
#pragma unroll
        for (int i = 0; i < 4; i++) aoff[i] = (uint32_t)((arow + i * 16) * 128 + acol);
#pragma unroll
        for (int j = 0; j < 4; j++) boff[j] = (uint32_t)((brow + j * 8) * 128 + bcol);
    }

    float c[4][4][4];
#pragma unroll
    for (int i = 0; i < 4; i++)
#pragma unroll
        for (int j = 0; j < 4; j++)
#pragma unroll
            for (int v = 0; v < 4; v++) c[i][j][v] = 0.0f;

    // prologue: fill STAGES-1 stages
#pragma unroll
    for (int s = 0; s < STAGES - 1; s++)
        load_tile(sA + s * TILE_BYTES, sB + s * TILE_BYTES, g_A, g_B, m0, n0, s * 64, tid);

    for (int kt = 0; kt < KITERS; ++kt) {
        cp_async_wait2();
        __syncthreads();

        // issue next stage loads (into the stage computed last iteration)
        {
            int nk = kt + STAGES - 1;
            if (nk < KITERS) {
                int ns = nk & (STAGES - 1);
                load_tile(sA + ns * TILE_BYTES, sB + ns * TILE_BYTES, g_A, g_B,
                          m0, n0, nk * 64, tid);
            } else {
                cp_async_commit();   // keep group accounting uniform
            }
        }

        const uint32_t aS = sA + (kt & (STAGES - 1)) * TILE_BYTES;
        const uint32_t bS = sB + (kt & (STAGES - 1)) * TILE_BYTES;

#pragma unroll
        for (int ks = 0; ks < 4; ks++) {
            uint32_t a[4][4], b[4][2];
#pragma unroll
            for (int i = 0; i < 4; i++) ldsm_x4(a[i], aS + SWZ(aoff[i] + ks * 32));
#pragma unroll
            for (int j = 0; j < 4; j++) ldsm_x2(b[j], bS + SWZ(boff[j] + ks * 32));
#pragma unroll
            for (int i = 0; i < 4; i++)
#pragma unroll
                for (int j = 0; j < 4; j++) mma16816(c[i][j], a[i], b[j]);
        }
    }

    // epilogue: c[i][j] regs -> out. Thread layout of m16n8 accum:
    // rows (l/4) and (l/4)+8, cols 2*(l%4), +1
    const int g = lid >> 2, tg = lid & 3;
#pragma unroll
    for (int i = 0; i < 4; i++) {
        int row0 = m0 + wm + i * 16 + g;
#pragma unroll
        for (int j = 0; j < 4; j++) {
            int col = n0 + wn + j * 8 + tg * 2;
            float2* p0 = reinterpret_cast<float2*>(out + (size_t)row0 * NN + col);
            float2* p1 = reinterpret_cast<float2*>(out + (size_t)(row0 + 8) * NN + col);
            *p0 = make_float2(c[i][j][0], c[i][j][1]);
            *p1 = make_float2(c[i][j][2], c[i][j][3]);
        }
    }
}

// ---------------------------------------------------------------------------
// Launch
// ---------------------------------------------------------------------------
extern "C" void kernel_launch(void* const* d_in, const int* in_sizes, int n_in,
                              void* d_out, int out_size) {
    const float* x      = (const float*)d_in[0];
    const int*   q      = (const int*)d_in[1];
    const float* scales = (const float*)d_in[2];
    const float* tables = (const float*)d_in[3];
    float* out = (float*)d_out;

    const int cvt_blocks = (int)(((size_t)MM * KK) / 4 / 256);   // 16384
    k_convert_x<<<cvt_blocks, 256>>>(x);
    k_dequant_w<<<cvt_blocks, 256>>>(q, scales, tables);

    cudaFuncSetAttribute(qgemm, cudaFuncAttributeMaxDynamicSharedMemorySize, SMEM_BYTES);
    dim3 grid(NN / 128, MM / 128);
    qgemm<<<grid, 256, SMEM_BYTES>>>(out);
}

// round 5
// speedup vs baseline: 1.1447x; 1.1447x over previous
#include <cuda_runtime.h>
#include <cuda_fp16.h>
#include <cstdint>
#include <cstddef>

// Problem dims (fixed for this dataset entry)
static constexpr int MM = 4096;
static constexpr int NN = 4096;
static constexpr int KK = 4096;
static constexpr int NG = 32;          // K / 128 groups

// fp16 staging buffers (static device globals: allowed scratch)
__device__ __half g_A[(size_t)MM * KK];   // x in fp16
__device__ __half g_B[(size_t)NN * KK];   // dequantized W in fp16

// ---------------------------------------------------------------------------
// Helpers (base-target PTX only)
// ---------------------------------------------------------------------------
__device__ __forceinline__ uint32_t smem_u32(const void* p) {
    uint32_t a;
    asm("{ .reg .u64 t; cvta.to.shared.u64 t, %1; cvt.u32.u64 %0, t; }"
        : "=r"(a) : "l"(p));
    return a;
}

__device__ __forceinline__ void cp_async16(uint32_t dst, const void* src) {
    asm volatile("cp.async.cg.shared.global [%0], [%1], 16;"
                 :: "r"(dst), "l"(src));
}
__device__ __forceinline__ void cp_async_commit() {
    asm volatile("cp.async.commit_group;" ::: "memory");
}
__device__ __forceinline__ void cp_async_wait1() {
    asm volatile("cp.async.wait_group 1;" ::: "memory");
}

__device__ __forceinline__ void ldsm_x4(uint32_t* r, uint32_t addr) {
    asm volatile("ldmatrix.sync.aligned.m8n8.x4.shared.b16 {%0,%1,%2,%3}, [%4];"
                 : "=r"(r[0]), "=r"(r[1]), "=r"(r[2]), "=r"(r[3]) : "r"(addr));
}
__device__ __forceinline__ void ldsm_x2(uint32_t* r, uint32_t addr) {
    asm volatile("ldmatrix.sync.aligned.m8n8.x2.shared.b16 {%0,%1}, [%2];"
                 : "=r"(r[0]), "=r"(r[1]) : "r"(addr));
}

__device__ __forceinline__ void mma16816(float* c, const uint32_t* a, const uint32_t* b) {
    asm volatile("mma.sync.aligned.m16n8k16.row.col.f32.f16.f16.f32 "
                 "{%0,%1,%2,%3}, {%4,%5,%6,%7}, {%8,%9}, {%0,%1,%2,%3};"
                 : "+f"(c[0]), "+f"(c[1]), "+f"(c[2]), "+f"(c[3])
                 : "r"(a[0]), "r"(a[1]), "r"(a[2]), "r"(a[3]),
                   "r"(b[0]), "r"(b[1]));
}

// SW128 swizzle: XOR bits [6:4] with bits [9:7]
#define SWZ(o) ((o) ^ (((o) >> 3) & 0x70))

// ---------------------------------------------------------------------------
// Stage 1 kernels: fp32 -> fp16 convert, and LUT dequant of W
// ---------------------------------------------------------------------------
__global__ void __launch_bounds__(256) k_convert_x(const float* __restrict__ x) {
    size_t i = (size_t)blockIdx.x * 256 + threadIdx.x;   // float4 index
    float4 v = reinterpret_cast<const float4*>(x)[i];
    __half2* o = reinterpret_cast<__half2*>(g_A) + i * 2;
    o[0] = __floats2half2_rn(v.x, v.y);
    o[1] = __floats2half2_rn(v.z, v.w);
}

__global__ void __launch_bounds__(256) k_dequant_w(const int* __restrict__ q,
                                                   const float* __restrict__ scales,
                                                   const float* __restrict__ tables) {
    __shared__ float t[16];
    if (threadIdx.x < 16) t[threadIdx.x] = tables[threadIdx.x];
    __syncthreads();
    size_t i = (size_t)blockIdx.x * 256 + threadIdx.x;   // int4 index (4 q values)
    int4 qv = reinterpret_cast<const int4*>(q)[i];
    size_t e = i * 4;                                    // flat element index
    int n = (int)(e >> 12);                              // /4096
    int k = (int)(e & 4095);
    float s = scales[(size_t)n * NG + (k >> 7)];
    __half2* o = reinterpret_cast<__half2*>(g_B) + i * 2;
    o[0] = __floats2half2_rn(t[qv.x] * s, t[qv.y] * s);
    o[1] = __floats2half2_rn(t[qv.z] * s, t[qv.w] * s);
}

// ---------------------------------------------------------------------------
// Stage 2: mma.sync (HMMA.16816) GEMM  y[M,N] = A[M,K] * B[N,K]^T
// CTA tile 128x128, BK=64, 3-stage cp.async pipeline, 2 CTAs/SM, 8 warps x (64x32)
// ---------------------------------------------------------------------------
static constexpr int STAGES = 3;
static constexpr int TILE_BYTES = 128 * 128;                  // 16KB per operand per stage
static constexpr int SMEM_BYTES = 1024 + STAGES * 2 * TILE_BYTES;  // 97KB: 2 CTAs fit
static constexpr int KITERS = KK / 64;                        // 64

__device__ __forceinline__ void load_tile(uint32_t sA, uint32_t sB,
                                          const __half* gA, const __half* gB,
                                          int m0, int n0, int k0, int tid) {
#pragma unroll
    for (int i = 0; i < 4; i++) {
        int ci = tid + (i << 8);            // 0..1023 chunk id
        int r = ci >> 3, c = ci & 7;        // row, 16B chunk within row
        uint32_t off = SWZ(r * 128 + c * 16);
        cp_async16(sA + off, gA + (size_t)(m0 + r) * KK + k0 + (c << 3));
        cp_async16(sB + off, gB + (size_t)(n0 + r) * KK + k0 + (c << 3));
    }
    cp_async_commit();
}

__global__ void __launch_bounds__(256, 2)
qgemm(float* __restrict__ out) {
    extern __shared__ __align__(1024) char smem[];
    uint32_t sb = (smem_u32(smem) + 1023) & ~1023u;
    const int tid = threadIdx.x, wid = tid >> 5, lid = tid & 31;
    const int m0 = blockIdx.y << 7, n0 = blockIdx.x << 7;

    const uint32_t sA = sb;                          // STAGES x 16KB
    const uint32_t sB = sb + STAGES * TILE_BYTES;    // STAGES x 16KB

    // warp tile: 64 (M) x 32 (N)
    const int wm = (wid & 1) << 6;       // 0 or 64
    const int wn = (wid >> 1) << 5;      // 0,32,64,96

    // per-thread ldmatrix byte offsets (pre-swizzle, within a stage tile)
    uint32_t aoff[4], boff[4];
    {
        int arow = wm + (lid & 15);
        int acol = (lid >> 4) << 4;                  // 0 or 16 bytes
        int blane = lid & 15;
        int brow = wn + (blane & 7);
        int bcol = ((blane >> 3) & 1) << 4;          // 0 or 16 bytes
#pragma unroll
        for (int i = 0; i < 4; i++) aoff[i] = (uint32_t)((arow + i * 16) * 128 + acol);
#pragma unroll
        for (int j = 0; j < 4; j++) boff[j] = (uint32_t)((brow + j * 8) * 128 + bcol);
    }

    float c[4][4][4];
#pragma unroll
    for (int i = 0; i < 4; i++)
#pragma unroll
        for (int j = 0; j < 4; j++)
#pragma unroll
            for (int v = 0; v < 4; v++) c[i][j][v] = 0.0f;

    // prologue: fill STAGES-1 stages
#pragma unroll
    for (int s = 0; s < STAGES - 1; s++)
        load_tile(sA + s * TILE_BYTES, sB + s * TILE_BYTES, g_A, g_B, m0, n0, s * 64, tid);

    for (int kt = 0; kt < KITERS; ++kt) {
        cp_async_wait1();
        __syncthreads();

        // issue next stage loads (into the stage computed in iteration kt-1)
        {
            int nk = kt + STAGES - 1;
            if (nk < KITERS) {
                int ns = nk % STAGES;
                load_tile(sA + ns * TILE_BYTES, sB + ns * TILE_BYTES, g_A, g_B,
                          m0, n0, nk * 64, tid);
            } else {
                cp_async_commit();   // keep group accounting uniform
            }
        }

        const uint32_t aS = sA + (kt % STAGES) * TILE_BYTES;
        const uint32_t bS = sB + (kt % STAGES) * TILE_BYTES;

#pragma unroll
        for (int ks = 0; ks < 4; ks++) {
            uint32_t a[4][4], b[4][2];
#pragma unroll
            for (int i = 0; i < 4; i++) ldsm_x4(a[i], aS + SWZ(aoff[i] + ks * 32));
#pragma unroll
            for (int j = 0; j < 4; j++) ldsm_x2(b[j], bS + SWZ(boff[j] + ks * 32));
#pragma unroll
            for (int i = 0; i < 4; i++)
#pragma unroll
                for (int j = 0; j < 4; j++) mma16816(c[i][j], a[i], b[j]);
        }
    }

    // epilogue: c[i][j] regs -> out. m16n8 accum layout:
    // rows (l/4) and (l/4)+8, cols 2*(l%4), +1
    const int g = lid >> 2, tg = lid & 3;
#pragma unroll
    for (int i = 0; i < 4; i++) {
        int row0 = m0 + wm + i * 16 + g;
#pragma unroll
        for (int j = 0; j < 4; j++) {
            int col = n0 + wn + j * 8 + tg * 2;
            float2* p0 = reinterpret_cast<float2*>(out + (size_t)row0 * NN + col);
            float2* p1 = reinterpret_cast<float2*>(out + (size_t)(row0 + 8) * NN + col);
            *p0 = make_float2(c[i][j][0], c[i][j][1]);
            *p1 = make_float2(c[i][j][2], c[i][j][3]);
        }
    }
}

// ---------------------------------------------------------------------------
// Launch
// ---------------------------------------------------------------------------
extern "C" void kernel_launch(void* const* d_in, const int* in_sizes, int n_in,
                              void* d_out, int out_size) {
    const float* x      = (const float*)d_in[0];
    const int*   q      = (const int*)d_in[1];
    const float* scales = (const float*)d_in[2];
    const float* tables = (const float*)d_in[3];
    float* out = (float*)d_out;

    const int cvt_blocks = (int)(((size_t)MM * KK) / 4 / 256);   // 16384
    k_convert_x<<<cvt_blocks, 256>>>(x);
    k_dequant_w<<<cvt_blocks, 256>>>(q, scales, tables);

    cudaFuncSetAttribute(qgemm, cudaFuncAttributeMaxDynamicSharedMemorySize, SMEM_BYTES);
    dim3 grid(NN / 128, MM / 128);
    qgemm<<<grid, 256, SMEM_BYTES>>>(out);
}